// round 1
// baseline (speedup 1.0000x reference)
#include <cuda_runtime.h>

#define B_SZ   2048
#define N_INST 8
#define N_FEAT 100
#define N_HID  40
#define NC     40
#define NM     41

#define BT   64      // batch tile per CTA
#define NTHR 160     // 16 tb-groups (4 b each) x 10 col-groups

// Precomputed G[i,c] = A[i,c] @ Bp[i,c]  : (8*40) x 100 x 40 floats = 5.12 MB
__device__ float g_G[N_INST * NC * N_FEAT * N_HID];

// ---------------------------------------------------------------------------
// Kernel 1: G[ic][f][h] = sum_m A[ic][f][m] * Bp[ic][m][h]
// ---------------------------------------------------------------------------
__global__ void compute_G_kernel(const float* __restrict__ A,
                                 const float* __restrict__ Bp) {
    __shared__ float As[N_FEAT * NM];   // 4100 floats
    __shared__ float Bs[NM * N_HID];    // 1640 floats
    const int ic = blockIdx.x;
    const float* Ap  = A  + (size_t)ic * N_FEAT * NM;
    const float* Bpp = Bp + (size_t)ic * NM * N_HID;
    for (int idx = threadIdx.x; idx < N_FEAT * NM; idx += blockDim.x) As[idx] = Ap[idx];
    for (int idx = threadIdx.x; idx < NM * N_HID; idx += blockDim.x) Bs[idx] = Bpp[idx];
    __syncthreads();
    for (int idx = threadIdx.x; idx < N_FEAT * N_HID; idx += blockDim.x) {
        const int f = idx / N_HID;
        const int h = idx % N_HID;
        float s = 0.f;
#pragma unroll
        for (int m = 0; m < NM; m++)
            s += As[f * NM + m] * Bs[m * N_HID + h];
        g_G[(size_t)ic * (N_FEAT * N_HID) + idx] = s;
    }
}

// ---------------------------------------------------------------------------
// Kernel 2: fused  h = sum_c m .* (x @ G_c)   then  out = relu(sum_c m .* (G_c @ h) + b)
// CTA: (b-tile of 64, instance i). SMEM layout (floats):
//   xsT [100][64]   6400
//   msT [ 40][64]   2560
//   hT  [ 40][64]   2560
//   hmT [ 40][64]   2560
//   Gs  [4096]      phase A: [f][40] ; phase B: [h][102] (padded, transposed)
// total 18176 floats = 72704 B dynamic smem
// ---------------------------------------------------------------------------
__global__ __launch_bounds__(NTHR, 3)
void tmsspd_main_kernel(const float* __restrict__ x,
                        const float* __restrict__ mask,
                        const float* __restrict__ bfin,
                        float* __restrict__ out) {
    extern __shared__ float sm[];
    float* xsT = sm;              // 6400
    float* msT = sm + 6400;       // 2560
    float* hT  = sm + 8960;       // 2560
    float* hmT = sm + 11520;      // 2560
    float* Gs  = sm + 14080;      // 4096

    const int i  = blockIdx.y;
    const int b0 = blockIdx.x * BT;
    const int t  = threadIdx.x;
    const int tb  = t & 15;       // 0..15  -> 4 batches each
    const int tg  = t >> 4;       // 0..9   -> col group
    const int tb4 = tb * 4;

    // Load x tile (coalesced global reads; strided smem writes are a one-time cost)
    for (int idx = t; idx < BT * N_FEAT; idx += NTHR) {
        const int bl = idx / N_FEAT;
        const int f  = idx % N_FEAT;
        xsT[f * BT + bl] = x[((size_t)(b0 + bl) * N_INST + i) * N_FEAT + f];
    }
    // Load mask tile
    for (int idx = t; idx < BT * NC; idx += NTHR) {
        const int bl = idx / NC;
        const int c  = idx % NC;
        msT[c * BT + bl] = mask[((size_t)(b0 + bl) * N_INST + i) * NC + c];
    }

    const float* Gbase = g_G + (size_t)i * NC * (N_FEAT * N_HID);

    // ------------------- Phase A: h (4b x 4h per thread) -------------------
    float hacc[4][4];
#pragma unroll
    for (int a = 0; a < 4; a++)
#pragma unroll
        for (int b = 0; b < 4; b++) hacc[a][b] = 0.f;

    for (int c = 0; c < NC; c++) {
        __syncthreads();   // previous Gs consumers done (and x/mask ready at c=0)
        {
            const float4* src = reinterpret_cast<const float4*>(Gbase + (size_t)c * (N_FEAT * N_HID));
            float4* dst = reinterpret_cast<float4*>(Gs);
            for (int idx = t; idx < (N_FEAT * N_HID) / 4; idx += NTHR) dst[idx] = src[idx];
        }
        __syncthreads();

        float dot[4][4];
#pragma unroll
        for (int a = 0; a < 4; a++)
#pragma unroll
            for (int b = 0; b < 4; b++) dot[a][b] = 0.f;

#pragma unroll 4
        for (int f = 0; f < N_FEAT; f++) {
            const float4 xv = *reinterpret_cast<const float4*>(&xsT[f * BT + tb4]);
            const float4 gv = *reinterpret_cast<const float4*>(&Gs[f * N_HID + tg * 4]);
            const float xr[4] = {xv.x, xv.y, xv.z, xv.w};
            const float gr[4] = {gv.x, gv.y, gv.z, gv.w};
#pragma unroll
            for (int bb = 0; bb < 4; bb++)
#pragma unroll
                for (int jj = 0; jj < 4; jj++)
                    dot[bb][jj] += xr[bb] * gr[jj];
        }

        const float4 mv = *reinterpret_cast<const float4*>(&msT[c * BT + tb4]);
        const float mr[4] = {mv.x, mv.y, mv.z, mv.w};
#pragma unroll
        for (int bb = 0; bb < 4; bb++)
#pragma unroll
            for (int jj = 0; jj < 4; jj++)
                hacc[bb][jj] += mr[bb] * dot[bb][jj];
    }

    // store h tile (transposed: hT[h][b])
#pragma unroll
    for (int jj = 0; jj < 4; jj++)
#pragma unroll
        for (int bb = 0; bb < 4; bb++)
            hT[(tg * 4 + jj) * BT + tb4 + bb] = hacc[bb][jj];

    // ------------------- Phase B: out (4b x 10f per thread) -------------------
    float oacc[4][10];
#pragma unroll
    for (int a = 0; a < 4; a++)
#pragma unroll
        for (int k = 0; k < 10; k++) oacc[a][k] = 0.f;

    const int tf10 = tg * 10;

    for (int c = 0; c < NC; c++) {
        __syncthreads();   // also ensures hT fully written at c=0
        // hm[h][b] = mask[b,c] * h[h][b]
        for (int idx = t; idx < N_HID * BT; idx += NTHR)
            hmT[idx] = hT[idx] * msT[c * BT + (idx & (BT - 1))];
        // Gs transposed with pad 102: Gs[h*102 + f] = G[c][f][h]
        {
            const float* src = Gbase + (size_t)c * (N_FEAT * N_HID);
            for (int idx = t; idx < N_FEAT * N_HID; idx += NTHR) {
                const int f = idx / N_HID;
                const int h = idx % N_HID;
                Gs[h * 102 + f] = src[idx];
            }
        }
        __syncthreads();

#pragma unroll 2
        for (int h = 0; h < N_HID; h++) {
            const float4 hv = *reinterpret_cast<const float4*>(&hmT[h * BT + tb4]);
            const float hr[4] = {hv.x, hv.y, hv.z, hv.w};
#pragma unroll
            for (int k2 = 0; k2 < 5; k2++) {
                const float2 g2 = *reinterpret_cast<const float2*>(&Gs[h * 102 + tf10 + 2 * k2]);
#pragma unroll
                for (int bb = 0; bb < 4; bb++) {
                    oacc[bb][2 * k2]     += hr[bb] * g2.x;
                    oacc[bb][2 * k2 + 1] += hr[bb] * g2.y;
                }
            }
        }
    }

    // epilogue: bias + relu + store
#pragma unroll
    for (int bb = 0; bb < 4; bb++) {
        const int bl = tb4 + bb;
        const size_t orow = ((size_t)(b0 + bl) * N_INST + i) * N_FEAT;
#pragma unroll
        for (int k = 0; k < 10; k++) {
            const int f = tf10 + k;
            const float v = oacc[bb][k] + bfin[i * N_FEAT + f];
            out[orow + f] = fmaxf(v, 0.f);
        }
    }
}

// ---------------------------------------------------------------------------
extern "C" void kernel_launch(void* const* d_in, const int* in_sizes, int n_in,
                              void* d_out, int out_size) {
    (void)in_sizes; (void)n_in; (void)out_size;
    const float* x    = (const float*)d_in[0];
    const float* mask = (const float*)d_in[1];
    const float* A    = (const float*)d_in[2];
    const float* Bp   = (const float*)d_in[3];
    const float* bfin = (const float*)d_in[4];
    float* out = (float*)d_out;

    const int smem_bytes = 18176 * 4;  // 72704
    cudaFuncSetAttribute(tmsspd_main_kernel,
                         cudaFuncAttributeMaxDynamicSharedMemorySize, smem_bytes);

    compute_G_kernel<<<N_INST * NC, 128>>>(A, Bp);

    dim3 grid(B_SZ / BT, N_INST);
    tmsspd_main_kernel<<<grid, NTHR, smem_bytes>>>(x, mask, bfin, out);
}